// round 3
// baseline (speedup 1.0000x reference)
#include <cuda_runtime.h>
#include <math.h>
#include <math_constants.h>

#define NS 4760
#define KNN 16
#define NB 16
#define NT 6

// ------------------------- device scratch -------------------------
__device__ float g_ql [NS*64];
__device__ float g_sp [NS*64];
__device__ float g_spW[NS*64];
__device__ float g_qg [NS*128];
__device__ float g_a0 [NS];
__device__ float g_a1 [NS];
__device__ float g_kg [NB*NT*128];
__device__ float g_vgo [NB*25*128];
__device__ float g_vgoW[NB*25*64];
__device__ float g_sumv[NB*25];
__device__ float g_gram[NB*25*25];
__device__ float g_gl  [(size_t)NS*NB*24];
__device__ float g_cst [256];   // [w0W(64) w1W(64) gcol(64) cadd(64)]

__device__ __forceinline__ float wsum(float v){
    #pragma unroll
    for (int o=16;o;o>>=1) v += __shfl_xor_sync(0xffffffffu, v, o);
    return v;
}
__device__ __forceinline__ float wmax(float v){
    #pragma unroll
    for (int o=16;o;o>>=1) v = fmaxf(v, __shfl_xor_sync(0xffffffffu, v, o));
    return v;
}

// ------------------------- K A: sensor static (+ consts in block 149) -------------------------
#define A_TS 32
__global__ void __launch_bounds__(256,1) kA(
    const float* __restrict__ pos, const float* __restrict__ femb, const int* __restrict__ fid,
    const float* __restrict__ Wnbr, const float* __restrict__ bnbr,
    const float* __restrict__ Wql,  const float* __restrict__ bql,
    const float* __restrict__ Wqg,  const float* __restrict__ bqg,
    const float* __restrict__ lng,  const float* __restrict__ Wm1,
    const float* __restrict__ lnb,  const float* __restrict__ bm1)
{
    extern __shared__ float sm[];
    int tid = threadIdx.x;

    if (blockIdx.x == 149){
        // fold of former k_consts
        if (tid < 64){
            int j = tid;
            float w0W=0.f, w1W=0.f, gcol=0.f, cadd=0.f;
            for (int i=0;i<192;i++){
                float w = Wm1[i*64+j];
                gcol += lng[i]*w;
                cadd += lnb[i]*w;
            }
            for (int i=0;i<64;i++){
                float w = lng[i]*Wm1[i*64+j];
                w0W += Wnbr[i]     * w;
                w1W += Wnbr[64+i]  * w;
            }
            g_cst[j]      = w0W;
            g_cst[64+j]   = w1W;
            g_cst[128+j]  = gcol;
            g_cst[192+j]  = cadd + bm1[j];
        }
        return;
    }

    float* sWql = sm;              // 8192
    float* sWnb = sm + 8192;       // 8192
    float* sWqg = sm + 16384;      // 16384
    float* sW1t = sm + 32768;      // 4096
    float* sQ   = sm + 36864;      // 32*128
    float* sSP  = sm + 40960;      // 32*64
    float* sQL  = sm + 43008;      // 32*64  (total 45056 floats)
    int n0 = blockIdx.x * A_TS;

    for (int e=tid;e<8192;e+=256){ sWql[e]=Wql[e]; sWnb[e]=Wnbr[128+e]; }
    for (int e=tid;e<16384;e+=256) sWqg[e]=Wqg[e];
    for (int e=tid;e<4096;e+=256)  sW1t[e]=lng[e>>6]*Wm1[e];
    for (int e=tid;e<4096;e+=256){
        int s=e>>7, i=e&127, n=n0+s;
        float v=0.f;
        if (n<NS) v = (i<96) ? pos[n*96+i] : femb[fid[n]*32 + (i-96)];
        sQ[e]=v;
    }
    __syncthreads();

    int c4 = (tid & 63)*4;       // col group of 4 in [0,256)
    int sbase = (tid >> 6)*8;    // 8 sensors
    const float* Wp; int ld, cc;
    if (c4 < 64)       { Wp=sWql; ld=64;  cc=c4; }
    else if (c4 < 128) { Wp=sWnb; ld=64;  cc=c4-64; }
    else               { Wp=sWqg; ld=128; cc=c4-128; }

    float acc[8][4];
    #pragma unroll
    for (int s=0;s<8;s++){ acc[s][0]=0.f; acc[s][1]=0.f; acc[s][2]=0.f; acc[s][3]=0.f; }

    for (int i=0;i<128;i++){
        float4 w = *(const float4*)(Wp + i*ld + cc);
        #pragma unroll
        for (int s=0;s<8;s++){
            float q = sQ[(sbase+s)*128 + i];
            acc[s][0] = fmaf(q, w.x, acc[s][0]);
            acc[s][1] = fmaf(q, w.y, acc[s][1]);
            acc[s][2] = fmaf(q, w.z, acc[s][2]);
            acc[s][3] = fmaf(q, w.w, acc[s][3]);
        }
    }
    #pragma unroll
    for (int u=0;u<4;u++){
        int col = c4+u;
        float bias;
        if (col<64) bias = bql[col];
        else if (col<128) bias = bnbr[col-64];
        else bias = bqg[col-128];
        #pragma unroll
        for (int s=0;s<8;s++){
            int n = n0 + sbase + s;
            float v = acc[s][u] + bias;
            if (col<64)       sQL[(sbase+s)*64+col]      = v;
            else if (col<128) sSP[(sbase+s)*64+(col-64)] = v;
            if (n < NS){
                if (col<64)       g_ql[n*64+col]        = v;
                else if (col<128) g_sp[n*64+(col-64)]   = v;
                else              g_qg[n*128+(col-128)] = v;
            }
        }
    }
    __syncthreads();

    // spW = sp @ W1g_top
    {
        int j4 = (tid & 15)*4;
        int s0 = (tid >> 4)*2;
        float a0_=0.f,a1_=0.f,a2_=0.f,a3_=0.f,b0_=0.f,b1_=0.f,b2_=0.f,b3_=0.f;
        for (int i=0;i<64;i++){
            float4 w = *(const float4*)(sW1t + i*64 + j4);
            float q0 = sSP[s0*64+i], q1 = sSP[(s0+1)*64+i];
            a0_=fmaf(q0,w.x,a0_); a1_=fmaf(q0,w.y,a1_); a2_=fmaf(q0,w.z,a2_); a3_=fmaf(q0,w.w,a3_);
            b0_=fmaf(q1,w.x,b0_); b1_=fmaf(q1,w.y,b1_); b2_=fmaf(q1,w.z,b2_); b3_=fmaf(q1,w.w,b3_);
        }
        int na = n0+s0, nb2 = n0+s0+1;
        if (na<NS){ g_spW[na*64+j4]=a0_; g_spW[na*64+j4+1]=a1_; g_spW[na*64+j4+2]=a2_; g_spW[na*64+j4+3]=a3_; }
        if (nb2<NS){ g_spW[nb2*64+j4]=b0_; g_spW[nb2*64+j4+1]=b1_; g_spW[nb2*64+j4+2]=b2_; g_spW[nb2*64+j4+3]=b3_; }
    }
    // a0/a1
    if (tid < 32){
        int n = n0 + tid;
        if (n < NS){
            float a0=0.f, a1=0.f;
            for (int i=0;i<64;i++){
                float q = sQL[tid*64+i];
                a0 = fmaf(Wnbr[i],    q, a0);
                a1 = fmaf(Wnbr[64+i], q, a1);
            }
            g_a0[n]=a0; g_a1[n]=a1;
        }
    }
}

// ------------------------- K D: per (b,t) latent path (256 thr, split dot) ----
__global__ void __launch_bounds__(256,1) kD(
    const float* __restrict__ latent, const float* __restrict__ femb,
    const float* __restrict__ Wlat, const float* __restrict__ blat,
    const float* __restrict__ Wlf,  const float* __restrict__ blf,
    const float* __restrict__ Wk,   const float* __restrict__ bk,
    const float* __restrict__ Wv,   const float* __restrict__ bv,
    const float* __restrict__ Wgo,  const float* __restrict__ bgo)
{
    __shared__ float lat_s[1056], part_s[2][128], kv_s[128], vg_s[128];
    int t = blockIdx.x, b = blockIdx.y, tid = threadIdx.x;
    for (int e=tid;e<1024;e+=256) lat_s[e] = latent[((size_t)b*NT+t)*1024 + e];
    if (tid<32) lat_s[1024+tid] = femb[t*32+tid];
    __syncthreads();

    int j = tid & 127, half = tid >> 7;
    float acc = half ? 0.f : (blat[j] + blf[j]);
    if (half == 0){
        #pragma unroll 4
        for (int i=0;i<512;i++) acc = fmaf(lat_s[i], Wlat[i*128+j], acc);
    } else {
        #pragma unroll 4
        for (int i=512;i<1024;i++) acc = fmaf(lat_s[i], Wlat[i*128+j], acc);
        for (int f=0;f<32;f++)     acc = fmaf(lat_s[1024+f], Wlf[f*128+j], acc);
    }
    part_s[half][j] = acc;
    __syncthreads();
    if (tid < 128) kv_s[tid] = part_s[0][tid] + part_s[1][tid];
    __syncthreads();

    // half 0: kg ; half 1: vg
    {
        const float* W  = half ? Wv : Wk;
        float o = half ? bv[j] : bk[j];
        #pragma unroll 4
        for (int i=0;i<128;i++) o = fmaf(kv_s[i], W[i*128+j], o);
        if (half == 0) g_kg[(b*NT+t)*128 + j] = o;
        else           vg_s[j] = o;
    }
    __syncthreads();

    // vgo: 4 heads x 128 j = 512 outputs, 2 per thread
    for (int o2=tid;o2<512;o2+=256){
        int h = o2 >> 7, j2 = o2 & 127;
        float a = 0.f;
        #pragma unroll
        for (int d=0;d<32;d++) a = fmaf(vg_s[h*32+d], Wgo[(h*32+d)*128+j2], a);
        g_vgo[((size_t)b*25 + t*4 + h)*128 + j2] = a;
    }
    if (t==0){
        for (int j2=tid;j2<128;j2+=256) g_vgo[((size_t)b*25 + 24)*128 + j2] = bgo[j2];
    }
}

// ------------------------- K E2: per-batch folds, warp-parallel dots ----------
__global__ void __launch_bounds__(256,1) kE2(const float* __restrict__ lng, const float* __restrict__ Wm1){
    extern __shared__ float sm[];
    float* vgo_s = sm;          // 25*132 = 3300
    float* w1bT  = sm + 3300;   // 64*132 = 8448   (total 11748 floats)
    int b = blockIdx.x, tid = threadIdx.x;
    for (int e=tid;e<3200;e+=256){ int i=e>>7, c=e&127; vgo_s[i*132+c] = g_vgo[(size_t)b*3200+e]; }
    for (int e=tid;e<8192;e+=256){ int c=e>>6, j=e&63; w1bT[j*132+c] = lng[64+c]*Wm1[4096+e]; }
    __syncthreads();

    int warp = tid >> 5, lane = tid & 31;
    int wg = blockIdx.y*8 + warp;   // 0..31
    int c4 = lane*4;

    for (int task=wg; task<2250; task+=32){
        if (task < 1600){
            int i = task >> 6, j = task & 63;
            float4 a = *(const float4*)(vgo_s + i*132 + c4);
            float4 w = *(const float4*)(w1bT  + j*132 + c4);
            float v = a.x*w.x + a.y*w.y + a.z*w.z + a.w*w.w;
            v = wsum(v);
            if (lane==0) g_vgoW[(b*25+i)*64 + j] = v;
        } else if (task < 2225){
            int p = task - 1600, i1 = p/25, i2 = p%25;
            float4 a = *(const float4*)(vgo_s + i1*132 + c4);
            float4 c = *(const float4*)(vgo_s + i2*132 + c4);
            float v = a.x*c.x + a.y*c.y + a.z*c.z + a.w*c.w;
            v = wsum(v);
            if (lane==0) g_gram[b*625 + p] = v;
        } else {
            int i = task - 2225;
            float4 a = *(const float4*)(vgo_s + i*132 + c4);
            float v = a.x + a.y + a.z + a.w;
            v = wsum(v);
            if (lane==0) g_sumv[b*25 + i] = v;
        }
    }
}

// ------------------------- K F: global logits as register-tiled GEMM ----------
// per h: gl[n, b*6+t] = (qg[n, h*32:..] . kg[b,t, h*32:..]) * 1/sqrt(32)
__global__ void __launch_bounds__(256,1) kF(){
    __shared__ float Qs[128*33];   // rows n, k
    __shared__ float Ks[96*33];    // rows (b*6+t), k
    int tid = threadIdx.x;
    int n0 = blockIdx.x * 128;
    int h  = blockIdx.y;

    for (int e=tid;e<4096;e+=256){
        int r=e>>5, k=e&31, n=n0+r;
        Qs[r*33+k] = (n<NS) ? g_qg[n*128 + h*32 + k] : 0.f;
    }
    for (int e=tid;e<3072;e+=256){
        int c=e>>5, k=e&31;
        Ks[c*33+k] = g_kg[c*128 + h*32 + k];
    }
    __syncthreads();

    int cg = tid & 15;          // batch b = cg
    int rg = tid >> 4;          // row group
    int r0 = rg*8;
    float acc[8][6];
    #pragma unroll
    for (int s=0;s<8;s++)
        #pragma unroll
        for (int u=0;u<6;u++) acc[s][u]=0.f;

    #pragma unroll 4
    for (int k=0;k<32;k++){
        float qv[8], kv[6];
        #pragma unroll
        for (int s=0;s<8;s++) qv[s] = Qs[(r0+s)*33 + k];
        #pragma unroll
        for (int u=0;u<6;u++) kv[u] = Ks[(cg*6+u)*33 + k];
        #pragma unroll
        for (int s=0;s<8;s++)
            #pragma unroll
            for (int u=0;u<6;u++) acc[s][u] = fmaf(qv[s], kv[u], acc[s][u]);
    }

    const float scale = 0.17677669529663687f;
    #pragma unroll
    for (int s=0;s<8;s++){
        int n = n0 + r0 + s;
        if (n >= NS) continue;
        #pragma unroll
        for (int u=0;u<6;u++)
            g_gl[((size_t)n*16 + cg)*24 + h*6 + u] = acc[s][u]*scale;
    }
}

// ------------------------- K G: fused main -------------------------
__global__ void __launch_bounds__(512,1) kG(
    const float* __restrict__ xf, const int* __restrict__ mask, const int* __restrict__ knn,
    const float* __restrict__ Wnbr, const float* __restrict__ Wm2, const float* __restrict__ bm2,
    float* __restrict__ out)
{
    extern __shared__ float sm[];
    float* vgoW_s = sm;            // 25600
    float* gram_s = sm + 25600;    // 10000
    float* sumv_s = sm + 35600;    // 400
    float* cst    = sm + 36000;    // 448
    int tid = threadIdx.x;
    for (int e=tid;e<25600;e+=512) vgoW_s[e] = g_vgoW[e];
    for (int e=tid;e<10000;e+=512) gram_s[e] = g_gram[e];
    if (tid < 400) sumv_s[tid] = g_sumv[tid];
    if (tid < 128) cst[tid] = Wnbr[tid];                 // w0 | w1
    if (tid >= 128 && tid < 384) cst[tid] = g_cst[tid-128]; // w0W w1W gcol cadd
    if (tid >= 384 && tid < 448) cst[tid] = Wm2[tid-384];
    __syncthreads();
    const float* w0_s  = cst;
    const float* w1_s  = cst + 64;
    const float* w0W_s = cst + 128;
    const float* w1W_s = cst + 192;
    const float* gcol_s= cst + 256;
    const float* cadd_s= cst + 320;
    const float* wm2_s = cst + 384;

    const unsigned FULL = 0xffffffffu;
    int wid = tid >> 5, lane = tid & 31;
    float bm2v = bm2[0];

    for (int n = blockIdx.x*16 + wid; n < NS; n += gridDim.x*16){
        int kj = 0;
        if (lane < 16) kj = knn[n*16 + lane];
        float a0 = g_a0[n], a1 = g_a1[n];
        float ql0 = g_ql[n*64 + lane], ql1 = g_ql[n*64 + 32 + lane];
        float rsp0[16], rsp1[16], rw0[16], rw1[16];
        #pragma unroll
        for (int k=0;k<16;k++){
            int j = __shfl_sync(FULL, kj, k);
            rsp0[k] = g_sp[j*64 + lane];
            rsp1[k] = g_sp[j*64 + 32 + lane];
            rw0[k]  = g_spW[j*64 + lane];
            rw1[k]  = g_spW[j*64 + 32 + lane];
        }
        float Sreg = 0.f;
        #pragma unroll
        for (int k=0;k<16;k++){
            float p = fmaf(rsp0[k], ql0, rsp1[k]*ql1);
            p = wsum(p);
            if (lane == k) Sreg = p;
        }

        for (int b=0;b<16;b++){
            // ---- local attention ----
            float x0 = 0.f, x1 = 0.f, logit = -CUDART_INF_F;
            if (lane < 16){
                float2 xv = *(const float2*)(xf + (size_t)(b*NS + kj)*2);
                x0 = xv.x; x1 = xv.y;
                int mk = mask[b*NS + kj];
                logit = (mk != 0) ? -10000.f : (Sreg + x0*a0 + x1*a1)*0.125f;
            }
            float mx  = wmax(logit);
            float e   = (lane < 16) ? __expf(logit - mx) : 0.f;
            float den = wsum(e);
            float sx0 = wsum(e*x0);
            float sx1 = wsum(e*x1);
            float inv = 1.f/den;
            float attn = e*inv;
            float alpha = sx0*inv, beta = sx1*inv;

            float L0 = alpha*w0_s[lane]      + beta*w1_s[lane];
            float L1 = alpha*w0_s[32+lane]   + beta*w1_s[32+lane];
            float P0 = alpha*w0W_s[lane]     + beta*w1W_s[lane];
            float P1 = alpha*w0W_s[32+lane]  + beta*w1W_s[32+lane];
            #pragma unroll
            for (int k=0;k<16;k++){
                float ak = __shfl_sync(FULL, attn, k);
                L0 = fmaf(ak, rsp0[k], L0);
                L1 = fmaf(ak, rsp1[k], L1);
                P0 = fmaf(ak, rw0[k],  P0);
                P1 = fmaf(ak, rw1[k],  P1);
            }
            float sL  = wsum(L0 + L1);
            float sL2 = wsum(L0*L0 + L1*L1);

            // ---- global attention ----
            float gl = (lane < 24) ? g_gl[((size_t)n*16 + b)*24 + lane] : 0.f;
            int hbase = (lane/6)*6; if (hbase > 24) hbase = 24;
            float m6 = -CUDART_INF_F;
            #pragma unroll
            for (int tt=0;tt<6;tt++){ float v = __shfl_sync(FULL, gl, hbase+tt); m6 = fmaxf(m6, v); }
            float eg = __expf(gl - m6);
            float s6 = 0.f;
            #pragma unroll
            for (int tt=0;tt<6;tt++) s6 += __shfl_sync(FULL, eg, hbase+tt);
            float ga = eg / s6;
            // remap lane order (h*6+t) -> row order (t*4+h)
            int src = (lane < 24) ? ((lane & 3)*6 + (lane >> 2)) : 0;
            float gsh = __shfl_sync(FULL, ga, src);
            float gaR = (lane < 24) ? gsh : ((lane == 24) ? 1.f : 0.f);

            int rowi = (lane < 25) ? lane : 0;
            float sumg = wsum(gaR * sumv_s[b*25 + rowi]);

            float rowd = 0.f;
            #pragma unroll
            for (int i2=0;i2<25;i2++){
                float gv = __shfl_sync(FULL, gaR, i2);
                rowd = fmaf(gv, gram_s[(b*25 + rowi)*25 + i2], rowd);
            }
            float sumg2 = wsum(gaR * rowd);

            float Pg0 = 0.f, Pg1 = 0.f;
            #pragma unroll
            for (int i=0;i<25;i++){
                float gv = __shfl_sync(FULL, gaR, i);
                Pg0 = fmaf(gv, vgoW_s[(b*25+i)*64 + lane],      Pg0);
                Pg1 = fmaf(gv, vgoW_s[(b*25+i)*64 + 32 + lane], Pg1);
            }

            // ---- LN + MLP fold ----
            float mean = (sL + sumg)*(1.f/192.f);
            float var  = (sL2 + sumg2)*(1.f/192.f) - mean*mean;
            float rstd = rsqrtf(var + 1e-5f);
            float h0 = fmaf(rstd, (P0+Pg0) - mean*gcol_s[lane],    cadd_s[lane]);
            float h1 = fmaf(rstd, (P1+Pg1) - mean*gcol_s[32+lane], cadd_s[32+lane]);
            float gelu0 = 0.5f*h0*(1.f + erff(h0*0.70710678118654752f));
            float gelu1 = 0.5f*h1*(1.f + erff(h1*0.70710678118654752f));
            float pr = wsum(fmaf(gelu0, wm2_s[lane], gelu1*wm2_s[32+lane]));
            if (lane == 0){
                int mn = mask[b*NS + n];
                out[b*NS + n] = mn ? (pr + bm2v) : 0.f;
            }
        }
    }
}

// ------------------------- launch -------------------------
extern "C" void kernel_launch(void* const* d_in, const int* in_sizes, int n_in,
                              void* d_out, int out_size){
    const float* xf    = (const float*)d_in[0];
    const float* latent= (const float*)d_in[1];
    const float* pos   = (const float*)d_in[2];
    const float* femb  = (const float*)d_in[3];
    const float* Wnbr  = (const float*)d_in[4];
    const float* bnbr  = (const float*)d_in[5];
    const float* Wql   = (const float*)d_in[6];
    const float* bql   = (const float*)d_in[7];
    const float* Wlat  = (const float*)d_in[8];
    const float* blat  = (const float*)d_in[9];
    const float* Wlf   = (const float*)d_in[10];
    const float* blf   = (const float*)d_in[11];
    const float* Wqg   = (const float*)d_in[12];
    const float* bqg   = (const float*)d_in[13];
    const float* Wk    = (const float*)d_in[14];
    const float* bk    = (const float*)d_in[15];
    const float* Wv    = (const float*)d_in[16];
    const float* bv    = (const float*)d_in[17];
    const float* Wgo   = (const float*)d_in[18];
    const float* bgo   = (const float*)d_in[19];
    const float* lng   = (const float*)d_in[20];
    const float* lnb   = (const float*)d_in[21];
    const float* Wm1   = (const float*)d_in[22];
    const float* bm1   = (const float*)d_in[23];
    const float* Wm2   = (const float*)d_in[24];
    const float* bm2   = (const float*)d_in[25];
    const int* mask    = (const int*)d_in[26];
    const int* knn     = (const int*)d_in[27];
    const int* fid     = (const int*)d_in[28];
    float* out = (float*)d_out;

    cudaFuncSetAttribute(kA,  cudaFuncAttributeMaxDynamicSharedMemorySize, 45056*4);
    cudaFuncSetAttribute(kE2, cudaFuncAttributeMaxDynamicSharedMemorySize, 11748*4);
    cudaFuncSetAttribute(kG,  cudaFuncAttributeMaxDynamicSharedMemorySize, 36448*4);

    kA<<<150,256,45056*4>>>(pos, femb, fid, Wnbr, bnbr, Wql, bql, Wqg, bqg, lng, Wm1, lnb, bm1);
    kD<<<dim3(6,16),256>>>(latent, femb, Wlat, blat, Wlf, blf, Wk, bk, Wv, bv, Wgo, bgo);
    kF<<<dim3(38,4),256>>>();
    kE2<<<dim3(16,4),256,11748*4>>>(lng, Wm1);
    kG<<<149,512,36448*4>>>(xf, mask, knn, Wnbr, Wm2, bm2, out);
}